// round 8
// baseline (speedup 1.0000x reference)
#include <cuda_runtime.h>

#define EPSF 1e-5f
#define NB   128   // 128 blocks < 148 SMs -> co-resident; per-batch barriers over 64 blocks

// Scratch (__device__ globals per allocation-free rule)
__device__ float4 g_xy4[2 * 64 * 256];    // [b][c/2][j] = {x(c0),y(c0),x(c1),y(c1)} normalized
__device__ float2 g_s2 [2 * 64 * 256];    // [b][o/2][j] = {s(o0), s(o1)}
__device__ unsigned g_flags[2][64];       // per-block generation flags (monotonic across replays)

// ---- packed f32x2 helpers ----
__device__ __forceinline__ unsigned long long pk2(float a, float b) {
    unsigned long long r;
    asm("mov.b64 %0, {%1, %2};" : "=l"(r) : "f"(a), "f"(b));
    return r;
}
__device__ __forceinline__ unsigned long long dup2(float a) {
    unsigned long long r;
    asm("mov.b64 %0, {%1, %1};" : "=l"(r) : "f"(a));
    return r;
}
__device__ __forceinline__ float2 upk2(unsigned long long v) {
    float a, b;
    asm("mov.b64 {%0, %1}, %2;" : "=f"(a), "=f"(b) : "l"(v));
    return make_float2(a, b);
}
__device__ __forceinline__ unsigned long long fma2(unsigned long long a,
                                                   unsigned long long b,
                                                   unsigned long long c) {
    unsigned long long r;
    asm("fma.rn.f32x2 %0, %1, %2, %3;" : "=l"(r) : "l"(a), "l"(b), "l"(c));
    return r;
}
__device__ __forceinline__ unsigned long long add2(unsigned long long a,
                                                   unsigned long long b) {
    unsigned long long r;
    asm("add.rn.f32x2 %0, %1, %2;" : "=l"(r) : "l"(a), "l"(b));
    return r;
}
__device__ __forceinline__ unsigned long long lds64(const float2* p) {
    return *(const unsigned long long*)p;
}

// Distributed flag barrier over the 64 blocks of batch bb.
// Arrival: release-store generation `target` to this block's own flag.
// Wait: threads 0..63 poll the 64 flags in parallel.
// Generations increase monotonically across graph replays (base read at entry).
__device__ __forceinline__ void flag_barrier(int bb, int ob, unsigned target) {
    __syncthreads();                       // all threads finished prior phase
    if (threadIdx.x == 0) {
        __threadfence();                   // publish this block's global writes
        *(volatile unsigned*)&g_flags[bb][ob] = target;
    }
    if (threadIdx.x < 64) {
        while ((int)(*(volatile unsigned*)&g_flags[bb][threadIdx.x] - target) < 0) { }
    }
    __syncthreads();
}

// Group-wide (256-thread) reduction of 4 values; two groups reduce concurrently
// in disjoint smem slices. All 512 threads must reach the syncs.
__device__ __forceinline__ void red4g(float a, float b, float c, float d,
                                      float* red /*[64]*/, float out[4],
                                      int lane, int gwid, int ch) {
#pragma unroll
    for (int o = 16; o > 0; o >>= 1) {
        a += __shfl_down_sync(0xffffffffu, a, o);
        b += __shfl_down_sync(0xffffffffu, b, o);
        c += __shfl_down_sync(0xffffffffu, c, o);
        d += __shfl_down_sync(0xffffffffu, d, o);
    }
    __syncthreads();
    if (lane == 0) {
        float* r = red + ch * 32;
        r[gwid] = a; r[8 + gwid] = b; r[16 + gwid] = c; r[24 + gwid] = d;
    }
    __syncthreads();
    const float* r = red + ch * 32;
    float t0 = 0.f, t1 = 0.f, t2 = 0.f, t3 = 0.f;
#pragma unroll
    for (int w = 0; w < 8; w++) {
        t0 += r[w]; t1 += r[8 + w]; t2 += r[16 + w]; t3 += r[24 + w];
    }
    out[0] = t0; out[1] = t1; out[2] = t2; out[3] = t3;
}

// ---------------------------------------------------------------------------
// One persistent kernel, 128 blocks x 512 threads.
//  phase 1: group g normalizes row bid*2+g of x (+pos) and y; stores its
//           {xn,yn} half directly into the packed float4 slot (no exchange).
//  phase 2: c-pair GEMV split 2 ways (LDG.128; packed f32x2 over channel pair),
//           separable inorm (b1 cancels; var = varA+varB),
//           s[i] = 128 b'_i + 0.5 sum_j |a'_j + b'_i|  (sum_j a'_j = 0),
//           packed-abs accumulation; paired store -> g_s2.
//  phase 3: o-pair loop split 2 ways (LDG.64; packed over output-channel pair).
// Barriers: distributed flag barrier per batch (64 blocks).
// ---------------------------------------------------------------------------
__global__ void __launch_bounds__(512, 1)
rn_fused(const float* __restrict__ x, const float* __restrict__ y,
         const float* __restrict__ pos, const float* __restrict__ w1,
         const float* __restrict__ w2, const float* __restrict__ b2,
         float* __restrict__ out) {
    __shared__ __align__(16) float2 s_wA[128];    // {Wi_o0[c], Wi_o1[c]}
    __shared__ __align__(16) float2 s_wB[128];    // {Wj_o0[c], Wj_o1[c]}
    __shared__ __align__(16) float2 s_wY[128];    // {Wy_o0[c], Wy_o1[c]}
    __shared__ __align__(16) float2 s_w2p[128];   // {w2_p0[o], w2_p1[o]}
    __shared__ __align__(16) float  s_as[512];    // a' per channel (float4-read)
    __shared__ __align__(16) float2 s_pa[512];    // packed partial exchange
    __shared__ __align__(16) float2 s_pb[512];
    __shared__ __align__(16) float  s_red[64];
    __shared__ float s_b2[2];

    const int tid  = threadIdx.x;          // 0..511
    const int g    = tid >> 8;             // group 0/1
    const int j    = tid & 255;
    const int lane = tid & 31;
    const int gwid = (tid >> 5) & 7;
    const int bid  = blockIdx.x;
    const int bb   = bid >> 6;             // batch
    const int ob   = bid & 63;             // block index within batch
    const int o0   = ob * 2;               // channel pair

    // epoch base for this run (own flag only ever written by this block)
    const unsigned base = g_flags[bb][ob];

    // ---- preload packed weights (first use after flag_barrier) ----
    if (tid < 128) {
        const float* w1r = w1 + o0 * 384;
        s_wA[tid]  = make_float2(w1r[tid],       w1r[384 + tid]);
        s_wB[tid]  = make_float2(w1r[128 + tid], w1r[512 + tid]);
        s_wY[tid]  = make_float2(w1r[256 + tid], w1r[640 + tid]);
        const float* w2r = w2 + o0 * 128;
        s_w2p[tid] = make_float2(w2r[tid], w2r[128 + tid]);
    }
    if (tid < 2) s_b2[tid] = b2[o0 + tid];

    // ---- phase 1: group g normalizes row idx = bid*2+g (x with pos, and y) ----
    {
        const int idx = bid * 2 + g;
        const int c   = idx & 127;
        float xv = x[idx * 256 + j] + pos[j * 128 + c];
        float yv = y[idx * 256 + j];
        float r[4];
        red4g(xv, xv * xv, yv, yv * yv, s_red, r, lane, gwid, g);
        const float inv = 1.f / 256.f;
        const float mx = r[0] * inv, my = r[2] * inv;
        const float rx = rsqrtf(r[1] * inv - mx * mx + EPSF);
        const float ry = rsqrtf(r[3] * inv - my * my + EPSF);
        const float xn = fmaxf((xv - mx) * rx, 0.f);
        const float yn = fmaxf((yv - my) * ry, 0.f);
        // direct 8B store into this group's half of the packed float4 slot
        ((float2*)&g_xy4[bid * 256 + j])[g] = make_float2(xn, yn);
    }

    flag_barrier(bb, ob, base + 1);

    // ---- phase 2: relate for (bb, o0) and (bb, o0+1) ----
    {
        const float4* __restrict__ xy = g_xy4 + bb * 16384;
        unsigned long long accA = 0ull, accB = 0ull;   // packed (ch0, ch1)
        const int pbase = g * 32;                      // c-pair range
#pragma unroll 8
        for (int pp = 0; pp < 32; pp++) {
            const int cp = pbase + pp;
            const float4 v = __ldcg(&xy[cp * 256 + j]);
            const int c0 = cp * 2;
            accA = fma2(lds64(&s_wA[c0]),     dup2(v.x), accA);
            accB = fma2(lds64(&s_wB[c0]),     dup2(v.x), accB);
            accB = fma2(lds64(&s_wY[c0]),     dup2(v.y), accB);
            accA = fma2(lds64(&s_wA[c0 + 1]), dup2(v.z), accA);
            accB = fma2(lds64(&s_wB[c0 + 1]), dup2(v.z), accB);
            accB = fma2(lds64(&s_wY[c0 + 1]), dup2(v.w), accB);
        }
        s_pa[tid] = upk2(accA);
        s_pb[tid] = upk2(accB);
        __syncthreads();

        // combine group partials; group index now selects output channel g
        float A, B;
        if (g == 0) { A = s_pa[j].x + s_pa[256 + j].x; B = s_pb[j].x + s_pb[256 + j].x; }
        else        { A = s_pa[j].y + s_pa[256 + j].y; B = s_pb[j].y + s_pb[256 + j].y; }

        float r[4];
        red4g(A, A * A, B, B * B, s_red, r, lane, gwid, g);
        const float inv = 1.f / 256.f;
        const float mA = r[0] * inv, mB = r[2] * inv;
        const float rs = rsqrtf((r[1] * inv - mA * mA) + (r[3] * inv - mB * mB) + EPSF);
        s_as[g * 256 + j] = (A - mA) * rs;
        const float bp  = (B - mB) * rs;
        __syncthreads();

        // s[i] = 128*bp + 0.5 * sum_j |a'_j + bp|   (packed abs via sign mask)
        const unsigned long long bp2  = dup2(bp);
        const unsigned long long ABS2 = 0x7FFFFFFF7FFFFFFFull;
        unsigned long long sabs2 = 0ull;
        const float4* a4 = (const float4*)(s_as + g * 256);
#pragma unroll 8
        for (int q = 0; q < 64; q++) {
            const float4 u = a4[q];
            sabs2 = add2(sabs2, add2(pk2(u.x, u.y), bp2) & ABS2);
            sabs2 = add2(sabs2, add2(pk2(u.z, u.w), bp2) & ABS2);
        }
        const float2 sv = upk2(sabs2);
        const float s_val = fmaf(128.f, bp, 0.5f * (sv.x + sv.y));
        ((float*)&g_s2[bid * 256 + j])[g] = s_val;   // paired store {s_o0, s_o1}
    }

    flag_barrier(bb, ob, base + 2);

    // ---- phase 3: out[bb, o0+{0,1}, :]; o-pair loop split 2 ways ----
    {
        const float2* __restrict__ sr = g_s2 + bb * 16384;
        unsigned long long acc = 0ull;                 // packed (p0, p1)
        const int kbase = g * 32;
#pragma unroll 8
        for (int kk = 0; kk < 32; kk++) {
            const int k = kbase + kk;
            const float2 sv = __ldcg(&sr[k * 256 + j]);
            acc = fma2(lds64(&s_w2p[2 * k]),     dup2(sv.x), acc);
            acc = fma2(lds64(&s_w2p[2 * k + 1]), dup2(sv.y), acc);
        }
        s_pa[tid] = upk2(acc);
        __syncthreads();

        const float part = (g == 0) ? (s_pa[j].x + s_pa[256 + j].x)
                                    : (s_pa[j].y + s_pa[256 + j].y);
        out[(bb * 128 + o0 + g) * 256 + j] = part + 256.f * s_b2[g];
    }
}

extern "C" void kernel_launch(void* const* d_in, const int* in_sizes, int n_in,
                              void* d_out, int out_size) {
    const float* x   = (const float*)d_in[0];   // (2,128,16,16)
    const float* y   = (const float*)d_in[1];   // (2,128,16,16)
    const float* pos = (const float*)d_in[2];   // (256,128)
    const float* w1  = (const float*)d_in[3];   // (128,384)
    // d_in[4] = b1 — provably unused (cancels in instance-norm centering)
    const float* w2  = (const float*)d_in[5];   // (128,128)
    const float* b2  = (const float*)d_in[6];   // (128,)
    float* out = (float*)d_out;                 // (2,128,16,16)

    rn_fused<<<NB, 512>>>(x, y, pos, w1, w2, b2, out);
}

// round 9
// speedup vs baseline: 1.2641x; 1.2641x over previous
#include <cuda_runtime.h>

#define EPSF 1e-5f
#define NB   128   // 128 blocks < 148 SMs -> co-resident; per-batch barriers over 64 blocks

// Scratch (__device__ globals per allocation-free rule)
__device__ float4 g_xy4[2 * 64 * 256];    // [b][c/2][j] = {x(c0),y(c0),x(c1),y(c1)} normalized
__device__ unsigned g_bar2[2] = {0, 0};
__device__ volatile unsigned g_gen2[2] = {0, 0};

// ---- packed f32x2 helpers ----
__device__ __forceinline__ unsigned long long pk2(float a, float b) {
    unsigned long long r;
    asm("mov.b64 %0, {%1, %2};" : "=l"(r) : "f"(a), "f"(b));
    return r;
}
__device__ __forceinline__ unsigned long long dup2(float a) {
    unsigned long long r;
    asm("mov.b64 %0, {%1, %1};" : "=l"(r) : "f"(a));
    return r;
}
__device__ __forceinline__ float2 upk2(unsigned long long v) {
    float a, b;
    asm("mov.b64 {%0, %1}, %2;" : "=f"(a), "=f"(b) : "l"(v));
    return make_float2(a, b);
}
__device__ __forceinline__ unsigned long long fma2(unsigned long long a,
                                                   unsigned long long b,
                                                   unsigned long long c) {
    unsigned long long r;
    asm("fma.rn.f32x2 %0, %1, %2, %3;" : "=l"(r) : "l"(a), "l"(b), "l"(c));
    return r;
}
__device__ __forceinline__ unsigned long long add2(unsigned long long a,
                                                   unsigned long long b) {
    unsigned long long r;
    asm("add.rn.f32x2 %0, %1, %2;" : "=l"(r) : "l"(a), "l"(b));
    return r;
}
__device__ __forceinline__ unsigned long long lds64(const float2* p) {
    return *(const unsigned long long*)p;
}

// Per-batch grid barrier over 64 blocks (R7 version: atomic counter + 1-thread
// spin; generation-based, graph-replay safe).
__device__ __forceinline__ void batch_barrier(int bb) {
    __syncthreads();
    if (threadIdx.x == 0) {
        __threadfence();
        unsigned gen = g_gen2[bb];
        if (atomicAdd(&g_bar2[bb], 1u) == 63u) {
            g_bar2[bb] = 0;
            __threadfence();
            g_gen2[bb] = gen + 1;
        } else {
            while (g_gen2[bb] == gen) { }
        }
    }
    __syncthreads();
}

// Group-wide (256-thread) reduction of 4 values; two groups reduce concurrently
// in disjoint smem slices. All 512 threads must reach the syncs.
__device__ __forceinline__ void red4g(float a, float b, float c, float d,
                                      float* red /*[64]*/, float out[4],
                                      int lane, int gwid, int ch) {
#pragma unroll
    for (int o = 16; o > 0; o >>= 1) {
        a += __shfl_down_sync(0xffffffffu, a, o);
        b += __shfl_down_sync(0xffffffffu, b, o);
        c += __shfl_down_sync(0xffffffffu, c, o);
        d += __shfl_down_sync(0xffffffffu, d, o);
    }
    __syncthreads();
    if (lane == 0) {
        float* r = red + ch * 32;
        r[gwid] = a; r[8 + gwid] = b; r[16 + gwid] = c; r[24 + gwid] = d;
    }
    __syncthreads();
    const float* r = red + ch * 32;
    float t0 = 0.f, t1 = 0.f, t2 = 0.f, t3 = 0.f;
#pragma unroll
    for (int w = 0; w < 8; w++) {
        t0 += r[w]; t1 += r[8 + w]; t2 += r[16 + w]; t3 += r[24 + w];
    }
    out[0] = t0; out[1] = t1; out[2] = t2; out[3] = t3;
}

// ---------------------------------------------------------------------------
// One persistent kernel, 128 blocks x 512 threads, ONE grid barrier.
//  phase 1: group g normalizes row bid*2+g of x (+pos) and y -> packed g_xy4;
//           also initializes out[b,p,i] = 256*b2[p] (1 element per thread).
//  barrier (per batch): orders g_xy4 stores AND out-init before phase 2.
//  phase 2: c-pair GEMV split 2 ways (LDG.128, packed f32x2 over channel pair),
//           separable inorm (b1 cancels; var = varA+varB),
//           s[i] = 128 b'_i + 0.5 sum_j |a'_j + b'_i|  (sum_j a'_j = 0);
//           then scatter w2[p,o0]*s0[i] + w2[p,o1]*s1[i] into out via RED.F32
//           (64 p per group) — replaces stored g_s + barrier + phase 3.
// ---------------------------------------------------------------------------
__global__ void __launch_bounds__(512, 1)
rn_fused(const float* __restrict__ x, const float* __restrict__ y,
         const float* __restrict__ pos, const float* __restrict__ w1,
         const float* __restrict__ w2, const float* __restrict__ b2,
         float* __restrict__ out) {
    __shared__ __align__(16) float2 s_wA[128];    // {Wi_o0[c], Wi_o1[c]}
    __shared__ __align__(16) float2 s_wB[128];    // {Wj_o0[c], Wj_o1[c]}
    __shared__ __align__(16) float2 s_wY[128];    // {Wy_o0[c], Wy_o1[c]}
    __shared__ __align__(16) float2 s_w2c[128];   // {w2[p,o0], w2[p,o1]} for all p
    __shared__ __align__(16) float  s_as[512];    // a' per channel (float4-read)
    __shared__ __align__(16) float2 s_pa[512];    // packed partial exchange
    __shared__ __align__(16) float2 s_pb[512];
    __shared__ __align__(16) float  s_ps[512];    // s exchange {ch0, ch1}
    __shared__ __align__(16) float  s_red[64];

    const int tid  = threadIdx.x;          // 0..511
    const int g    = tid >> 8;             // group 0/1
    const int j    = tid & 255;
    const int lane = tid & 31;
    const int gwid = (tid >> 5) & 7;
    const int bid  = blockIdx.x;
    const int bb   = bid >> 6;             // batch
    const int o0   = (bid & 63) * 2;       // channel pair

    // ---- preload packed weights (first use after barrier / phase-2 tail) ----
    if (tid < 128) {
        const float* w1r = w1 + o0 * 384;
        s_wA[tid]  = make_float2(w1r[tid],       w1r[384 + tid]);
        s_wB[tid]  = make_float2(w1r[128 + tid], w1r[512 + tid]);
        s_wY[tid]  = make_float2(w1r[256 + tid], w1r[640 + tid]);
        // w2 column pair (stride-128 gather, 2 words per thread; tiny)
        s_w2c[tid] = make_float2(w2[tid * 128 + o0], w2[tid * 128 + o0 + 1]);
    }

    // ---- out init: out[b,p,i] = 256*b2[p]; this block owns 512 contiguous elems ----
    {
        const int idx = bid * 512 + tid;          // global out index (batch bb's range)
        out[idx] = 256.f * __ldg(&b2[(idx >> 8) & 127]);
    }

    // ---- phase 1: group g normalizes row idx = bid*2+g (x with pos, and y) ----
    {
        const int idx = bid * 2 + g;
        const int c   = idx & 127;
        float xv = x[idx * 256 + j] + pos[j * 128 + c];
        float yv = y[idx * 256 + j];
        float r[4];
        red4g(xv, xv * xv, yv, yv * yv, s_red, r, lane, gwid, g);
        const float inv = 1.f / 256.f;
        const float mx = r[0] * inv, my = r[2] * inv;
        const float rx = rsqrtf(r[1] * inv - mx * mx + EPSF);
        const float ry = rsqrtf(r[3] * inv - my * my + EPSF);
        const float xn = fmaxf((xv - mx) * rx, 0.f);
        const float yn = fmaxf((yv - my) * ry, 0.f);
        ((float2*)&g_xy4[bid * 256 + j])[g] = make_float2(xn, yn);
    }

    batch_barrier(bb);

    // ---- phase 2: relate for (bb, o0) and (bb, o0+1), then RED-scatter ----
    {
        const float4* __restrict__ xy = g_xy4 + bb * 16384;
        unsigned long long accA = 0ull, accB = 0ull;   // packed (ch0, ch1)
        const int pbase = g * 32;                      // c-pair range
#pragma unroll 8
        for (int pp = 0; pp < 32; pp++) {
            const int cp = pbase + pp;
            const float4 v = __ldcg(&xy[cp * 256 + j]);
            const int c0 = cp * 2;
            accA = fma2(lds64(&s_wA[c0]),     dup2(v.x), accA);
            accB = fma2(lds64(&s_wB[c0]),     dup2(v.x), accB);
            accB = fma2(lds64(&s_wY[c0]),     dup2(v.y), accB);
            accA = fma2(lds64(&s_wA[c0 + 1]), dup2(v.z), accA);
            accB = fma2(lds64(&s_wB[c0 + 1]), dup2(v.z), accB);
            accB = fma2(lds64(&s_wY[c0 + 1]), dup2(v.w), accB);
        }
        s_pa[tid] = upk2(accA);
        s_pb[tid] = upk2(accB);
        __syncthreads();

        // combine group partials; group index now selects output channel g
        float A, B;
        if (g == 0) { A = s_pa[j].x + s_pa[256 + j].x; B = s_pb[j].x + s_pb[256 + j].x; }
        else        { A = s_pa[j].y + s_pa[256 + j].y; B = s_pb[j].y + s_pb[256 + j].y; }

        float r[4];
        red4g(A, A * A, B, B * B, s_red, r, lane, gwid, g);
        const float inv = 1.f / 256.f;
        const float mA = r[0] * inv, mB = r[2] * inv;
        const float rs = rsqrtf((r[1] * inv - mA * mA) + (r[3] * inv - mB * mB) + EPSF);
        s_as[g * 256 + j] = (A - mA) * rs;
        const float bp  = (B - mB) * rs;
        __syncthreads();

        // s[i] = 128*bp + 0.5 * sum_j |a'_j + bp|   (packed abs via sign mask)
        const unsigned long long bp2  = dup2(bp);
        const unsigned long long ABS2 = 0x7FFFFFFF7FFFFFFFull;
        unsigned long long sabs2 = 0ull;
        const float4* a4 = (const float4*)(s_as + g * 256);
#pragma unroll 8
        for (int q = 0; q < 64; q++) {
            const float4 u = a4[q];
            sabs2 = add2(sabs2, add2(pk2(u.x, u.y), bp2) & ABS2);
            sabs2 = add2(sabs2, add2(pk2(u.z, u.w), bp2) & ABS2);
        }
        const float2 sv = upk2(sabs2);
        const float s_val = fmaf(128.f, bp, 0.5f * (sv.x + sv.y));

        // exchange s between channels at equal j
        s_ps[g * 256 + j] = s_val;
        __syncthreads();
        const float s0 = s_ps[j], s1 = s_ps[256 + j];

        // scatter contribution of channels (o0, o0+1) into out (fire-and-forget REDs)
        float* op = out + bb * 32768 + j;
        const int p0 = g * 64;
#pragma unroll 4
        for (int pp = 0; pp < 64; pp++) {
            const int p = p0 + pp;
            const float2 wv = s_w2c[p];
            atomicAdd(op + p * 256, fmaf(wv.x, s0, wv.y * s1));
        }
    }
}

extern "C" void kernel_launch(void* const* d_in, const int* in_sizes, int n_in,
                              void* d_out, int out_size) {
    const float* x   = (const float*)d_in[0];   // (2,128,16,16)
    const float* y   = (const float*)d_in[1];   // (2,128,16,16)
    const float* pos = (const float*)d_in[2];   // (256,128)
    const float* w1  = (const float*)d_in[3];   // (128,384)
    // d_in[4] = b1 — provably unused (cancels in instance-norm centering)
    const float* w2  = (const float*)d_in[5];   // (128,128)
    const float* b2  = (const float*)d_in[6];   // (128,)
    float* out = (float*)d_out;                 // (2,128,16,16)

    rn_fused<<<NB, 512>>>(x, y, pos, w1, w2, b2, out);
}

// round 10
// speedup vs baseline: 1.7438x; 1.3795x over previous
#include <cuda_runtime.h>

#define EPSF 1e-5f
#define NB   128   // 128 blocks < 148 SMs -> co-resident; per-batch barriers over 64 blocks

// Scratch (__device__ globals per allocation-free rule)
__device__ float4 g_xy4[2 * 64 * 256];    // [b][c/2][j] = {x(c0),y(c0),x(c1),y(c1)} normalized
__device__ float2 g_s2 [2 * 64 * 256];    // [b][o/2][j] = {s(o0), s(o1)}
__device__ unsigned g_bar2[2] = {0, 0};
__device__ volatile unsigned g_gen2[2] = {0, 0};

// ---- packed f32x2 helpers ----
__device__ __forceinline__ unsigned long long pk2(float a, float b) {
    unsigned long long r;
    asm("mov.b64 %0, {%1, %2};" : "=l"(r) : "f"(a), "f"(b));
    return r;
}
__device__ __forceinline__ unsigned long long dup2(float a) {
    unsigned long long r;
    asm("mov.b64 %0, {%1, %1};" : "=l"(r) : "f"(a));
    return r;
}
__device__ __forceinline__ float2 upk2(unsigned long long v) {
    float a, b;
    asm("mov.b64 {%0, %1}, %2;" : "=f"(a), "=f"(b) : "l"(v));
    return make_float2(a, b);
}
__device__ __forceinline__ unsigned long long fma2(unsigned long long a,
                                                   unsigned long long b,
                                                   unsigned long long c) {
    unsigned long long r;
    asm("fma.rn.f32x2 %0, %1, %2, %3;" : "=l"(r) : "l"(a), "l"(b), "l"(c));
    return r;
}
__device__ __forceinline__ unsigned long long add2(unsigned long long a,
                                                   unsigned long long b) {
    unsigned long long r;
    asm("add.rn.f32x2 %0, %1, %2;" : "=l"(r) : "l"(a), "l"(b));
    return r;
}
__device__ __forceinline__ unsigned long long lds64(const float2* p) {
    return *(const unsigned long long*)p;
}

// Per-batch grid barrier over 64 blocks (atomic counter + 1-thread spin;
// generation-based, graph-replay safe). R7-proven.
__device__ __forceinline__ void batch_barrier(int bb) {
    __syncthreads();
    if (threadIdx.x == 0) {
        __threadfence();
        unsigned gen = g_gen2[bb];
        if (atomicAdd(&g_bar2[bb], 1u) == 63u) {
            g_bar2[bb] = 0;
            __threadfence();
            g_gen2[bb] = gen + 1;
        } else {
            while (g_gen2[bb] == gen) { }
        }
    }
    __syncthreads();
}

// Group-wide (256-thread) reduction of 4 values; two groups reduce concurrently
// in disjoint smem slices. All 512 threads must reach the syncs.
__device__ __forceinline__ void red4g(float a, float b, float c, float d,
                                      float* red /*[64]*/, float out[4],
                                      int lane, int gwid, int ch) {
#pragma unroll
    for (int o = 16; o > 0; o >>= 1) {
        a += __shfl_down_sync(0xffffffffu, a, o);
        b += __shfl_down_sync(0xffffffffu, b, o);
        c += __shfl_down_sync(0xffffffffu, c, o);
        d += __shfl_down_sync(0xffffffffu, d, o);
    }
    __syncthreads();
    if (lane == 0) {
        float* r = red + ch * 32;
        r[gwid] = a; r[8 + gwid] = b; r[16 + gwid] = c; r[24 + gwid] = d;
    }
    __syncthreads();
    const float* r = red + ch * 32;
    float t0 = 0.f, t1 = 0.f, t2 = 0.f, t3 = 0.f;
#pragma unroll
    for (int w = 0; w < 8; w++) {
        t0 += r[w]; t1 += r[8 + w]; t2 += r[16 + w]; t3 += r[24 + w];
    }
    out[0] = t0; out[1] = t1; out[2] = t2; out[3] = t3;
}

// ---------------------------------------------------------------------------
// One persistent kernel, 128 blocks x 512 threads (R7 structure).
// KEY CHANGE vs R7: per-block ROTATED iteration order in the phase-2 c-pair
// stream and the phase-3 o-pair stream. All 64 blocks of a batch previously
// swept identical addresses in lockstep, serializing on single L2 slices; the
// rotation (ob-dependent start, any 2-partition of the 64 pairs is valid since
// group partials are summed) spreads requests across all LTS slices.
// ---------------------------------------------------------------------------
__global__ void __launch_bounds__(512, 1)
rn_fused(const float* __restrict__ x, const float* __restrict__ y,
         const float* __restrict__ pos, const float* __restrict__ w1,
         const float* __restrict__ w2, const float* __restrict__ b2,
         float* __restrict__ out) {
    __shared__ __align__(16) float2 s_wA[128];    // {Wi_o0[c], Wi_o1[c]}
    __shared__ __align__(16) float2 s_wB[128];    // {Wj_o0[c], Wj_o1[c]}
    __shared__ __align__(16) float2 s_wY[128];    // {Wy_o0[c], Wy_o1[c]}
    __shared__ __align__(16) float2 s_w2p[128];   // {w2_p0[o], w2_p1[o]}
    __shared__ __align__(16) float  s_as[512];    // a' per channel (float4-read)
    __shared__ __align__(16) float2 s_pa[512];    // packed partial exchange
    __shared__ __align__(16) float2 s_pb[512];
    __shared__ __align__(16) float  s_red[64];
    __shared__ float s_b2[2];

    const int tid  = threadIdx.x;          // 0..511
    const int g    = tid >> 8;             // group 0/1
    const int j    = tid & 255;
    const int lane = tid & 31;
    const int gwid = (tid >> 5) & 7;
    const int bid  = blockIdx.x;
    const int bb   = bid >> 6;             // batch
    const int ob   = bid & 63;             // block index within batch
    const int o0   = ob * 2;               // channel pair

    // ---- preload packed weights (first use after batch_barrier) ----
    if (tid < 128) {
        const float* w1r = w1 + o0 * 384;
        s_wA[tid]  = make_float2(w1r[tid],       w1r[384 + tid]);
        s_wB[tid]  = make_float2(w1r[128 + tid], w1r[512 + tid]);
        s_wY[tid]  = make_float2(w1r[256 + tid], w1r[640 + tid]);
        const float* w2r = w2 + o0 * 128;
        s_w2p[tid] = make_float2(w2r[tid], w2r[128 + tid]);
    }
    if (tid < 2) s_b2[tid] = b2[o0 + tid];

    // ---- phase 1: group g normalizes row idx = bid*2+g (x with pos, and y) ----
    {
        const int idx = bid * 2 + g;
        const int c   = idx & 127;
        float xv = x[idx * 256 + j] + pos[j * 128 + c];
        float yv = y[idx * 256 + j];
        float r[4];
        red4g(xv, xv * xv, yv, yv * yv, s_red, r, lane, gwid, g);
        const float inv = 1.f / 256.f;
        const float mx = r[0] * inv, my = r[2] * inv;
        const float rx = rsqrtf(r[1] * inv - mx * mx + EPSF);
        const float ry = rsqrtf(r[3] * inv - my * my + EPSF);
        const float xn = fmaxf((xv - mx) * rx, 0.f);
        const float yn = fmaxf((yv - my) * ry, 0.f);
        ((float2*)&g_xy4[bid * 256 + j])[g] = make_float2(xn, yn);
    }

    batch_barrier(bb);

    // ---- phase 2: relate for (bb, o0) and (bb, o0+1), rotated c-pair order ----
    {
        const float4* __restrict__ xy = g_xy4 + bb * 16384;
        unsigned long long accA = 0ull, accB = 0ull;   // packed (ch0, ch1)
        const int cstart = ob + g * 32;                // per-block rotation
#pragma unroll 8
        for (int pp = 0; pp < 32; pp++) {
            const int cp = (cstart + pp) & 63;
            const float4 v = __ldcg(&xy[cp * 256 + j]);
            const int c0 = cp * 2;
            accA = fma2(lds64(&s_wA[c0]),     dup2(v.x), accA);
            accB = fma2(lds64(&s_wB[c0]),     dup2(v.x), accB);
            accB = fma2(lds64(&s_wY[c0]),     dup2(v.y), accB);
            accA = fma2(lds64(&s_wA[c0 + 1]), dup2(v.z), accA);
            accB = fma2(lds64(&s_wB[c0 + 1]), dup2(v.z), accB);
            accB = fma2(lds64(&s_wY[c0 + 1]), dup2(v.w), accB);
        }
        s_pa[tid] = upk2(accA);
        s_pb[tid] = upk2(accB);
        __syncthreads();

        // combine: own partial from registers + peer group's from smem
        const float2 ownA = upk2(accA), ownB = upk2(accB);
        const float2 peerA = s_pa[(tid + 256) & 511];
        const float2 peerB = s_pb[(tid + 256) & 511];
        float A, B;
        if (g == 0) { A = ownA.x + peerA.x; B = ownB.x + peerB.x; }
        else        { A = ownA.y + peerA.y; B = ownB.y + peerB.y; }

        float r[4];
        red4g(A, A * A, B, B * B, s_red, r, lane, gwid, g);
        const float inv = 1.f / 256.f;
        const float mA = r[0] * inv, mB = r[2] * inv;
        const float rs = rsqrtf((r[1] * inv - mA * mA) + (r[3] * inv - mB * mB) + EPSF);
        s_as[g * 256 + j] = (A - mA) * rs;
        const float bp  = (B - mB) * rs;
        __syncthreads();

        // s[i] = 128*bp + 0.5 * sum_j |a'_j + bp|   (packed abs via sign mask)
        const unsigned long long bp2  = dup2(bp);
        const unsigned long long ABS2 = 0x7FFFFFFF7FFFFFFFull;
        unsigned long long sabs2 = 0ull;
        const float4* a4 = (const float4*)(s_as + g * 256);
#pragma unroll 8
        for (int q = 0; q < 64; q++) {
            const float4 u = a4[q];
            sabs2 = add2(sabs2, add2(pk2(u.x, u.y), bp2) & ABS2);
            sabs2 = add2(sabs2, add2(pk2(u.z, u.w), bp2) & ABS2);
        }
        const float2 sv = upk2(sabs2);
        const float s_val = fmaf(128.f, bp, 0.5f * (sv.x + sv.y));
        ((float*)&g_s2[bid * 256 + j])[g] = s_val;   // paired store {s_o0, s_o1}
    }

    batch_barrier(bb);

    // ---- phase 3: out[bb, o0+{0,1}, :]; rotated o-pair order ----
    {
        const float2* __restrict__ sr = g_s2 + bb * 16384;
        unsigned long long acc = 0ull;                 // packed (p0, p1)
        const int kstart = ob + g * 32;                // per-block rotation
#pragma unroll 8
        for (int kk = 0; kk < 32; kk++) {
            const int k = (kstart + kk) & 63;
            const float2 sv = __ldcg(&sr[k * 256 + j]);
            acc = fma2(lds64(&s_w2p[2 * k]),     dup2(sv.x), acc);
            acc = fma2(lds64(&s_w2p[2 * k + 1]), dup2(sv.y), acc);
        }
        s_pa[tid] = upk2(acc);
        __syncthreads();

        const float2 own  = upk2(acc);
        const float2 peer = s_pa[(tid + 256) & 511];
        const float part  = (g == 0) ? (own.x + peer.x) : (own.y + peer.y);
        out[(bb * 128 + o0 + g) * 256 + j] = part + 256.f * s_b2[g];
    }
}

extern "C" void kernel_launch(void* const* d_in, const int* in_sizes, int n_in,
                              void* d_out, int out_size) {
    const float* x   = (const float*)d_in[0];   // (2,128,16,16)
    const float* y   = (const float*)d_in[1];   // (2,128,16,16)
    const float* pos = (const float*)d_in[2];   // (256,128)
    const float* w1  = (const float*)d_in[3];   // (128,384)
    // d_in[4] = b1 — provably unused (cancels in instance-norm centering)
    const float* w2  = (const float*)d_in[5];   // (128,128)
    const float* b2  = (const float*)d_in[6];   // (128,)
    float* out = (float*)d_out;                 // (2,128,16,16)

    rn_fused<<<NB, 512>>>(x, y, pos, w1, w2, b2, out);
}